// round 2
// baseline (speedup 1.0000x reference)
#include <cuda_runtime.h>
#include <cstdint>
#include <math.h>

#define NC 128
#define NT 256
#define B 32
#define H 512
#define D 256
#define T 2048
#define V 32
#define L 100
#define G3 1536

// ---------------- device scratch (no allocation allowed) ----------------
__device__ float g_score[B * T];        // enc_score -> softmax weights (in place)
__device__ float g_ctxp[4 * B * D];     // partial ctx over t-chunks
__device__ float g_ctx[B * D];          // ctx
__device__ float g_gie[V * G3];         // emb@W_ih_e^T table (per token)
__device__ float g_gic[B * G3];         // ctx@W_ih_c^T + b_ih (per batch)
__device__ float g_h[2][B * H];         // ping-pong hidden state
__device__ int g_tok[B];                // current token
__device__ unsigned int g_cnt;          // grid barrier counter (monotonic)

__global__ void reset_kernel() { g_cnt = 0u; }

// monotonic grid barrier: every CTA calls it the same number of times
__device__ __forceinline__ void gbar(unsigned int &epoch) {
    epoch++;
    __threadfence();
    __syncthreads();
    if (threadIdx.x == 0) {
        atomicAdd(&g_cnt, 1u);
        unsigned int target = epoch * NC;
        unsigned int v;
        for (;;) {
            asm volatile("ld.acquire.gpu.u32 %0, [%1];" : "=r"(v) : "l"(&g_cnt) : "memory");
            if (v >= target) break;
            __nanosleep(64);
        }
    }
    __syncthreads();
}

extern "C" __global__ void __launch_bounds__(NT, 1) decoder_kernel(
    const float* __restrict__ enc,    // (T, B, D)
    const float* __restrict__ emb,    // (V, D)
    const float* __restrict__ W_attn, // (H+D, 1)
    const float* __restrict__ b_attn, // (1,)  -- unused (softmax shift-invariance)
    const float* __restrict__ W_ih,   // (3H, 2D)
    const float* __restrict__ W_hh,   // (3H, H)
    const float* __restrict__ b_ih,   // (3H,)
    const float* __restrict__ b_hh,   // (3H,)
    const float* __restrict__ W_out,  // (V, H)
    const float* __restrict__ b_out,  // (V,)
    float* __restrict__ out)          // (B, L, V)
{
    extern __shared__ float sm[];
    float* sH = sm;                 // 16384 floats: h (32 x 512)
    float* sW = sm + 16384;         // 6144 floats: W_hh tile [3 gates][4 j][512]
    float* sR = sm + 16384 + 6144;  // 6144 floats: reductions / misc

    const int tid = threadIdx.x;
    const int cta = blockIdx.x;
    unsigned int epoch = 0;

    // ------- persistent W_hh tile into smem (constant across all steps) -------
    {
        const int j0 = cta * 4;
        for (int idx = tid; idx < 12 * H; idx += NT) {
            int row = idx >> 9;      // 0..11
            int d = idx & (H - 1);
            int g = row >> 2, jj = row & 3;
            sW[idx] = W_hh[((size_t)(g * H + j0 + jj)) * H + d];
        }
    }

    // ------- P0: enc_score[b][t] = sum_d enc[t][b][d] * W_e[d] -------
    {
        const float4* w4 = reinterpret_cast<const float4*>(W_attn + H);
        for (int o = cta * NT + tid; o < B * T; o += NC * NT) {
            int b = o >> 11, t = o & (T - 1);
            const float4* e4 = reinterpret_cast<const float4*>(enc + ((size_t)t * B + b) * D);
            float acc = 0.f;
#pragma unroll 8
            for (int q = 0; q < D / 4; ++q) {
                float4 ev = e4[q], wv = w4[q];
                acc += ev.x * wv.x + ev.y * wv.y + ev.z * wv.z + ev.w * wv.w;
            }
            g_score[o] = acc;
        }
    }
    gbar(epoch);

    // ------- P1: row softmax over t (aw stored in place) -------
    if (cta < B) {
        const int b = cta;
        float m = -3.4e38f;
        for (int t = tid; t < T; t += NT) m = fmaxf(m, g_score[b * T + t]);
        sR[tid] = m;
        __syncthreads();
        for (int w = NT / 2; w > 0; w >>= 1) {
            if (tid < w) sR[tid] = fmaxf(sR[tid], sR[tid + w]);
            __syncthreads();
        }
        float mx = sR[0];
        __syncthreads();
        float sum = 0.f;
        for (int t = tid; t < T; t += NT) {
            float e = expf(g_score[b * T + t] - mx);
            g_score[b * T + t] = e;
            sum += e;
        }
        sR[tid] = sum;
        __syncthreads();
        for (int w = NT / 2; w > 0; w >>= 1) {
            if (tid < w) sR[tid] += sR[tid + w];
            __syncthreads();
        }
        float inv = 1.f / sR[0];
        __syncthreads();
        for (int t = tid; t < T; t += NT) g_score[b * T + t] *= inv;
    }
    gbar(epoch);

    // ------- P2: ctx partials over 4 t-chunks -------
    {
        int b = cta & 31, ch = cta >> 5;
        int d = tid;  // NT == D
        float acc = 0.f;
        int t0 = ch * (T / 4);
#pragma unroll 4
        for (int t = t0; t < t0 + T / 4; ++t)
            acc += __ldcg(&g_score[b * T + t]) * enc[((size_t)t * B + b) * D + d];
        g_ctxp[(ch * B + b) * D + d] = acc;
    }
    gbar(epoch);

    // ------- P2b: reduce ctx; init h0 = 0, tok = SOS -------
    if (cta < B) {
        int b = cta, d = tid;
        float acc = 0.f;
#pragma unroll
        for (int ch = 0; ch < 4; ++ch) acc += __ldcg(&g_ctxp[(ch * B + b) * D + d]);
        g_ctx[b * D + d] = acc;
    } else if (cta == 32) {
        for (int k = tid; k < B * H; k += NT) g_h[0][k] = 0.f;
    } else if (cta == 33) {
        if (tid < B) g_tok[tid] = 1;  // SOS
    }
    gbar(epoch);

    // ------- P3: gie[v][k] = emb[v]@W_ih[k,:D];  gic[b][k] = b_ih[k] + ctx[b]@W_ih[k,D:] -------
    {
        for (int o = cta * NT + tid; o < (V + B) * G3; o += NC * NT) {
            if (o < V * G3) {
                int v = o / G3, k = o - v * G3;
                const float4* er = reinterpret_cast<const float4*>(emb + (size_t)v * D);
                const float4* wr = reinterpret_cast<const float4*>(W_ih + (size_t)k * (2 * D));
                float acc = 0.f;
#pragma unroll 8
                for (int q = 0; q < D / 4; ++q) {
                    float4 ev = er[q], wv = wr[q];
                    acc += ev.x * wv.x + ev.y * wv.y + ev.z * wv.z + ev.w * wv.w;
                }
                g_gie[o] = acc;
            } else {
                int o2 = o - V * G3;
                int b = o2 / G3, k = o2 - b * G3;
                const float* cr = g_ctx + b * D;
                const float4* wr = reinterpret_cast<const float4*>(W_ih + (size_t)k * (2 * D) + D);
                float acc = b_ih[k];
#pragma unroll 8
                for (int q = 0; q < D / 4; ++q) {
                    float4 wv = wr[q];
                    acc += __ldcg(&cr[q * 4 + 0]) * wv.x + __ldcg(&cr[q * 4 + 1]) * wv.y +
                           __ldcg(&cr[q * 4 + 2]) * wv.z + __ldcg(&cr[q * 4 + 3]) * wv.w;
                }
                g_gic[o2] = acc;
            }
        }
    }
    gbar(epoch);

    // ------- main loop: 100 strictly sequential GRU steps -------
    const int s = tid & 15;        // 16-way d split
    const int tile = tid >> 4;     // 16 tiles: (jj, bg)
    const int jj = tile >> 2;      // 0..3 local j
    const int bg = tile & 3;       // 0..3 b-group (8 b each)
    const int j0 = cta * 4;

    int cur = 0;
    for (int it = 1; it <= L; ++it) {
        // ===== Phase A: h_new = GRU(h, tok)  (all 128 CTAs) =====
        {
            // broadcast h into smem (L2 reads; L1 may be stale -> ldcg)
            const float4* hsrc = reinterpret_cast<const float4*>(g_h[cur]);
            float4* hdst = reinterpret_cast<float4*>(sH);
#pragma unroll
            for (int k = tid; k < B * H / 4; k += NT) hdst[k] = __ldcg(hsrc + k);
            __syncthreads();

            const float2* hp = reinterpret_cast<const float2*>(sH);
            const float2* wp = reinterpret_cast<const float2*>(sW);
            const float2* hb = hp + (bg * 8) * (H / 2);

            float2 a0[8], a1[8], a2[8];
#pragma unroll
            for (int k = 0; k < 8; ++k) {
                a0[k] = make_float2(0.f, 0.f);
                a1[k] = make_float2(0.f, 0.f);
                a2[k] = make_float2(0.f, 0.f);
            }
#pragma unroll
            for (int i = 0; i < 16; ++i) {
                int dp = i * 16 + s;  // float2 index, conflict-free across lanes
                float2 w0 = wp[(0 * 4 + jj) * (H / 2) + dp];
                float2 w1 = wp[(1 * 4 + jj) * (H / 2) + dp];
                float2 w2 = wp[(2 * 4 + jj) * (H / 2) + dp];
#pragma unroll
                for (int k = 0; k < 8; ++k) {
                    float2 h2 = hb[k * (H / 2) + dp];
                    a0[k].x += h2.x * w0.x; a0[k].y += h2.y * w0.y;
                    a1[k].x += h2.x * w1.x; a1[k].y += h2.y * w1.y;
                    a2[k].x += h2.x * w2.x; a2[k].y += h2.y * w2.y;
                }
            }
            // partial reduction into smem
#pragma unroll
            for (int k = 0; k < 8; ++k) {
                int base = (tile * 24 + k * 3) * 16 + s;
                sR[base]      = a0[k].x + a0[k].y;
                sR[base + 16] = a1[k].x + a1[k].y;
                sR[base + 32] = a2[k].x + a2[k].y;
            }
            __syncthreads();

            if (tid < 128) {
                int tl = tid >> 3, kb = tid & 7;
                int jjo = tl >> 2, bgo = tl & 3;
                int b = bgo * 8 + kb, j = j0 + jjo;
                float gr = 0.f, gz = 0.f, gn = 0.f;
                int base = (tl * 24 + kb * 3) * 16;
#pragma unroll
                for (int q = 0; q < 16; ++q) {
                    gr += sR[base + q];
                    gz += sR[base + 16 + q];
                    gn += sR[base + 32 + q];
                }
                gr += b_hh[j];
                gz += b_hh[H + j];
                gn += b_hh[2 * H + j];
                int tk = __ldcg(&g_tok[b]);
                float ir  = g_gie[tk * G3 + j]         + g_gic[b * G3 + j];
                float iz  = g_gie[tk * G3 + H + j]     + g_gic[b * G3 + H + j];
                float in_ = g_gie[tk * G3 + 2 * H + j] + g_gic[b * G3 + 2 * H + j];
                float r = 1.f / (1.f + expf(-(ir + gr)));
                float z = 1.f / (1.f + expf(-(iz + gz)));
                float n = tanhf(in_ + r * gn);
                float hold = sH[b * H + j];
                g_h[cur ^ 1][b * H + j] = (1.f - z) * n + z * hold;
            }
        }
        gbar(epoch);

        // ===== Phase B: logits + argmax (CTAs 0..31, one per batch row) =====
        if (cta < B) {
            const int b = cta;
            const float* hr = g_h[cur ^ 1] + b * H;
            for (int k = tid; k < H; k += NT) sH[k] = __ldcg(hr + k);
            __syncthreads();
            int v = tid >> 3, p = tid & 7;
            const float* wr = W_out + (size_t)v * H + p * 64;
            const float* hh = sH + p * 64;
            float part = 0.f;
#pragma unroll 16
            for (int d2 = 0; d2 < 64; ++d2) part += hh[d2] * wr[d2];
            sR[v * 8 + p] = part;
            __syncthreads();
            if (tid < V) {
                float pr = b_out[tid];
#pragma unroll
                for (int p2 = 0; p2 < 8; ++p2) pr += sR[tid * 8 + p2];
                sR[256 + tid] = pr;
                out[((size_t)b * L + (it - 1)) * V + tid] = pr;
            }
            __syncthreads();
            if (tid == 0) {
                float best = sR[256];
                int bi = 0;
                for (int v2 = 1; v2 < V; ++v2) {
                    float x = sR[256 + v2];
                    if (x > best) { best = x; bi = v2; }  // first-max, matches jnp.argmax
                }
                g_tok[b] = bi;
            }
        }
        cur ^= 1;
        if (it < L) gbar(epoch);
    }
}

#define SMEM_BYTES ((16384 + 6144 + 6144) * 4)

extern "C" void kernel_launch(void* const* d_in, const int* in_sizes, int n_in,
                              void* d_out, int out_size) {
    const float* enc    = (const float*)d_in[0];
    const float* emb    = (const float*)d_in[1];
    const float* W_attn = (const float*)d_in[2];
    const float* b_attn = (const float*)d_in[3];
    const float* W_ih   = (const float*)d_in[4];
    const float* W_hh   = (const float*)d_in[5];
    const float* b_ih   = (const float*)d_in[6];
    const float* b_hh   = (const float*)d_in[7];
    const float* W_out  = (const float*)d_in[8];
    const float* b_out  = (const float*)d_in[9];
    float* out = (float*)d_out;

    cudaFuncSetAttribute(decoder_kernel, cudaFuncAttributeMaxDynamicSharedMemorySize, SMEM_BYTES);
    reset_kernel<<<1, 1>>>();
    decoder_kernel<<<NC, NT, SMEM_BYTES>>>(enc, emb, W_attn, b_attn, W_ih, W_hh,
                                           b_ih, b_hh, W_out, b_out, out);
}

// round 3
// speedup vs baseline: 2.7699x; 2.7699x over previous
#include <cuda_runtime.h>
#include <cstdint>
#include <math.h>

#define NC 144
#define NT 256
#define B 32
#define H 512
#define D 256
#define T 2048
#define V 32
#define L 100
#define G3 1536

// smem layout (floats)
#define OFF_H 0          // 32 rows x 516 (padded) = 16512
#define OFF_W 16512      // up to 3*4*512 = 6144
#define OFF_R 22656      // 12*4*33 = 1584 (reductions; aliased by phase-B buffers)
#define SMEM_FLOATS 24240
#define SMEM_BYTES (SMEM_FLOATS * 4)

// ---------------- device scratch ----------------
__device__ float g_score[B * T];
__device__ float g_ctxp[4 * B * D];
__device__ float g_ctx[B * D];
__device__ float g_gie[V * G3];
__device__ float g_gic[B * G3];
__device__ float g_h[2][B * H];
__device__ unsigned int g_tokflag[B];   // (step<<8) | tok
__device__ unsigned int g_cnt;

__global__ void reset_kernel() { g_cnt = 0u; }

// single monotonic grid barrier: release-red arrive + acquire spin
__device__ __forceinline__ void gbar(unsigned int &epoch) {
    epoch++;
    __threadfence();
    __syncthreads();
    if (threadIdx.x == 0) {
        asm volatile("red.release.gpu.add.u32 [%0], %1;" :: "l"(&g_cnt), "r"(1u) : "memory");
        unsigned int target = epoch * NC, v;
        do {
            asm volatile("ld.acquire.gpu.u32 %0, [%1];" : "=r"(v) : "l"(&g_cnt) : "memory");
        } while (v < target);
    }
    __syncthreads();
}

// ---------------- per-step GEMM + GRU finalize ----------------
// mapping: lane = b (32 batches) -> d-reduction stays in-thread.
// warps: (warp&1) selects a jj-group of NJW columns; (warp>>2? no: warp>>1) = d-quarter.
template<int JC>
__device__ __forceinline__ void do_gemm(float* sm, int tid, int it, int jbase, int dst,
                                        float bh0, float bh1, float bh2) {
    const int lane = tid & 31;
    const int warp = tid >> 5;
    constexpr int NJW = JC / 2;            // 2 (heavy) or 1 (light)
    const int jj0 = (warp & 1) * NJW;
    const int dh = warp >> 1;              // 0..3: 128-float d-quarter

    const ulonglong2* sH2 = (const ulonglong2*)(sm + OFF_H);
    const ulonglong2* sW2 = (const ulonglong2*)(sm + OFF_W);
    float* sR = sm + OFF_R;

    unsigned long long acc[NJW][3];
#pragma unroll
    for (int q = 0; q < NJW; ++q)
#pragma unroll
        for (int g = 0; g < 3; ++g) acc[q][g] = 0ULL;

    const ulonglong2* hrow = sH2 + lane * 129 + dh * 32;   // row stride 516 floats = 129 u2
    const ulonglong2* wq = sW2 + dh * 32;
#pragma unroll
    for (int c = 0; c < 32; ++c) {
        ulonglong2 h4 = hrow[c];
#pragma unroll
        for (int q = 0; q < NJW; ++q) {
#pragma unroll
            for (int g = 0; g < 3; ++g) {
                ulonglong2 w4 = wq[(g * JC + jj0 + q) * 128 + c];  // warp-broadcast
                asm("fma.rn.f32x2 %0, %1, %2, %0;" : "+l"(acc[q][g]) : "l"(h4.x), "l"(w4.x));
                asm("fma.rn.f32x2 %0, %1, %2, %0;" : "+l"(acc[q][g]) : "l"(h4.y), "l"(w4.y));
            }
        }
    }
#pragma unroll
    for (int q = 0; q < NJW; ++q)
#pragma unroll
        for (int g = 0; g < 3; ++g) {
            unsigned long long v = acc[q][g];
            float s = __uint_as_float((unsigned)v) + __uint_as_float((unsigned)(v >> 32));
            sR[(((jj0 + q) * 3 + g) * 4 + dh) * 33 + lane] = s;
        }
    __syncthreads();

    // finalize: thread (fj=warp<JC, b=lane) owns one h_new element
    if (tid < JC * 32) {
        const int b = lane, fj = warp;
        const int j = jbase + fj;
        float c0 = g_gic[b * G3 + j];
        float c1 = g_gic[b * G3 + 512 + j];
        float c2 = g_gic[b * G3 + 1024 + j];
        float gr = bh0, gz = bh1, gn = bh2;
#pragma unroll
        for (int d2 = 0; d2 < 4; ++d2) {
            gr += sR[((fj * 3 + 0) * 4 + d2) * 33 + b];
            gz += sR[((fj * 3 + 1) * 4 + d2) * 33 + b];
            gn += sR[((fj * 3 + 2) * 4 + d2) * 33 + b];
        }
        unsigned f;
        do {
            asm volatile("ld.acquire.gpu.u32 %0, [%1];" : "=r"(f) : "l"(g_tokflag + b) : "memory");
        } while ((f >> 8) != (unsigned)it);
        int tk = (int)(f & 255u);
        float e0 = g_gie[tk * G3 + j];
        float e1 = g_gie[tk * G3 + 512 + j];
        float e2 = g_gie[tk * G3 + 1024 + j];
        float rr = 1.f / (1.f + expf(-(e0 + c0 + gr)));
        float zz = 1.f / (1.f + expf(-(e1 + c1 + gz)));
        float nn = tanhf(e2 + c2 + rr * gn);
        float hold = sm[OFF_H + b * 516 + j];
        g_h[dst][b * H + j] = (1.f - zz) * nn + zz * hold;
    }
}

// ---------------- phase B: logits + argmax + tok publish (light CTAs) ----------------
__device__ __forceinline__ void phase_b(float* sm, int tid, int cta, int it, int dst,
                                        const float* __restrict__ W_out,
                                        const float* __restrict__ b_out,
                                        float* __restrict__ out) {
    float* sB = sm + OFF_R;
    if (tid < 128)
        ((float4*)sB)[tid] = __ldcg((const float4*)(g_h[dst] + cta * H) + tid);
    __syncthreads();
    const int lane = tid & 31, warp = tid >> 5;
    const int v0 = warp * 4;
    const float* w0 = W_out + (size_t)v0 * H;
    float a0 = 0.f, a1 = 0.f, a2 = 0.f, a3 = 0.f;
#pragma unroll
    for (int dd = 0; dd < 16; ++dd) {
        int d = dd * 32 + lane;
        float hv = sB[d];
        a0 += hv * __ldg(w0 + d);
        a1 += hv * __ldg(w0 + 512 + d);
        a2 += hv * __ldg(w0 + 1024 + d);
        a3 += hv * __ldg(w0 + 1536 + d);
    }
#pragma unroll
    for (int o = 16; o; o >>= 1) {
        a0 += __shfl_down_sync(0xffffffffu, a0, o);
        a1 += __shfl_down_sync(0xffffffffu, a1, o);
        a2 += __shfl_down_sync(0xffffffffu, a2, o);
        a3 += __shfl_down_sync(0xffffffffu, a3, o);
    }
    if (lane == 0) {
        sB[520 + v0 + 0] = a0 + b_out[v0 + 0];
        sB[520 + v0 + 1] = a1 + b_out[v0 + 1];
        sB[520 + v0 + 2] = a2 + b_out[v0 + 2];
        sB[520 + v0 + 3] = a3 + b_out[v0 + 3];
    }
    __syncthreads();
    if (tid < V) out[((size_t)cta * L + (it - 1)) * V + tid] = sB[520 + tid];
    if (tid == 0) {
        float best = sB[520];
        int bi = 0;
#pragma unroll
        for (int v = 1; v < V; ++v) {
            float x = sB[520 + v];
            if (x > best) { best = x; bi = v; }
        }
        unsigned fl = ((unsigned)(it + 1) << 8) | (unsigned)bi;
        asm volatile("st.release.gpu.u32 [%0], %1;" :: "l"(g_tokflag + cta), "r"(fl) : "memory");
    }
}

template<int JC>
__device__ void main_loop(float* sm, int tid, int cta, int jbase,
                          const float* __restrict__ b_hh,
                          const float* __restrict__ W_out,
                          const float* __restrict__ b_out,
                          float* __restrict__ out, unsigned &epoch) {
    float bh0 = 0.f, bh1 = 0.f, bh2 = 0.f;
    if (tid < JC * 32) {
        int j = jbase + (tid >> 5);
        bh0 = b_hh[j]; bh1 = b_hh[512 + j]; bh2 = b_hh[1024 + j];
    }
    int src = 0;
    for (int it = 1; it <= L; ++it) {
        const int dst = src ^ 1;
        // broadcast h (L2, bypass L1) into padded smem
        const float4* hs = (const float4*)g_h[src];
        float4* hd = (float4*)(sm + OFF_H);
#pragma unroll
        for (int k = tid; k < 4096; k += NT) {
            int b = k >> 7, c = k & 127;
            hd[b * 129 + c] = __ldcg(hs + k);
        }
        __syncthreads();
        do_gemm<JC>(sm, tid, it, jbase, dst, bh0, bh1, bh2);
        gbar(epoch);   // single barrier per step (includes threadfence)
        if constexpr (JC == 2) phase_b(sm, tid, cta, it, dst, W_out, b_out, out);
        src = dst;
    }
}

extern "C" __global__ void __launch_bounds__(NT, 1) decoder_kernel(
    const float* __restrict__ enc, const float* __restrict__ emb,
    const float* __restrict__ W_attn, const float* __restrict__ b_attn,
    const float* __restrict__ W_ih, const float* __restrict__ W_hh,
    const float* __restrict__ b_ih, const float* __restrict__ b_hh,
    const float* __restrict__ W_out, const float* __restrict__ b_out,
    float* __restrict__ out) {
    extern __shared__ float sm[];
    const int tid = threadIdx.x;
    const int cta = blockIdx.x;
    unsigned epoch = 0;
    const bool light = (cta < 32);
    const int JCr = light ? 2 : 4;
    const int jbase = light ? cta * 2 : 64 + (cta - 32) * 4;

    // persistent W_hh slice -> smem: rows [g][jj] of 512 floats
    for (int idx = tid; idx < 3 * JCr * 512; idx += NT) {
        int r = idx >> 9, d = idx & 511;
        int g = light ? (r >> 1) : (r >> 2);
        int jj = light ? (r & 1) : (r & 3);
        sm[OFF_W + idx] = W_hh[((size_t)(g * H + jbase + jj)) * H + d];
    }

    // ---- P0: enc_score[b][t] ----
    {
        const float4* w4 = reinterpret_cast<const float4*>(W_attn + H);
        for (int o = cta * NT + tid; o < B * T; o += NC * NT) {
            int b = o >> 11, t = o & (T - 1);
            const float4* e4 = reinterpret_cast<const float4*>(enc + ((size_t)t * B + b) * D);
            float acc = 0.f;
#pragma unroll 8
            for (int q = 0; q < D / 4; ++q) {
                float4 ev = e4[q], wv = w4[q];
                acc += ev.x * wv.x + ev.y * wv.y + ev.z * wv.z + ev.w * wv.w;
            }
            g_score[o] = acc;
        }
    }
    gbar(epoch);

    // ---- P1: softmax rows ----
    if (cta < B) {
        float* sR = sm + OFF_R;
        const int b = cta;
        float m = -3.4e38f;
        for (int t = tid; t < T; t += NT) m = fmaxf(m, g_score[b * T + t]);
        sR[tid] = m;
        __syncthreads();
        for (int w = NT / 2; w > 0; w >>= 1) {
            if (tid < w) sR[tid] = fmaxf(sR[tid], sR[tid + w]);
            __syncthreads();
        }
        float mx = sR[0];
        __syncthreads();
        float sum = 0.f;
        for (int t = tid; t < T; t += NT) {
            float e = expf(g_score[b * T + t] - mx);
            g_score[b * T + t] = e;
            sum += e;
        }
        sR[tid] = sum;
        __syncthreads();
        for (int w = NT / 2; w > 0; w >>= 1) {
            if (tid < w) sR[tid] += sR[tid + w];
            __syncthreads();
        }
        float inv = 1.f / sR[0];
        __syncthreads();
        for (int t = tid; t < T; t += NT) g_score[b * T + t] *= inv;
    }
    gbar(epoch);

    // ---- P2: ctx partials ----
    if (cta < 128) {
        int b = cta & 31, ch = cta >> 5;
        int d = tid;
        float acc = 0.f;
        int t0 = ch * (T / 4);
#pragma unroll 4
        for (int t = t0; t < t0 + T / 4; ++t)
            acc += __ldcg(&g_score[b * T + t]) * enc[((size_t)t * B + b) * D + d];
        g_ctxp[(ch * B + b) * D + d] = acc;
    }
    gbar(epoch);

    // ---- P2b: reduce ctx; init h0, tok flags ----
    if (cta < B) {
        int b = cta, d = tid;
        float acc = 0.f;
#pragma unroll
        for (int ch = 0; ch < 4; ++ch) acc += __ldcg(&g_ctxp[(ch * B + b) * D + d]);
        g_ctx[b * D + d] = acc;
    } else if (cta == 32) {
        for (int k = tid; k < B * H / 4; k += NT) ((float4*)g_h[0])[k] = make_float4(0.f, 0.f, 0.f, 0.f);
    } else if (cta == 33) {
        if (tid < B) g_tokflag[tid] = (1u << 8) | 1u;  // step 1, SOS
    }
    gbar(epoch);

    // ---- P3: gie / gic tables ----
    {
        for (int o = cta * NT + tid; o < (V + B) * G3; o += NC * NT) {
            if (o < V * G3) {
                int v = o / G3, k = o - v * G3;
                const float4* er = reinterpret_cast<const float4*>(emb + (size_t)v * D);
                const float4* wr = reinterpret_cast<const float4*>(W_ih + (size_t)k * (2 * D));
                float acc = 0.f;
#pragma unroll 8
                for (int q = 0; q < D / 4; ++q) {
                    float4 ev = er[q], wv = wr[q];
                    acc += ev.x * wv.x + ev.y * wv.y + ev.z * wv.z + ev.w * wv.w;
                }
                g_gie[o] = acc;
            } else {
                int o2 = o - V * G3;
                int b = o2 / G3, k = o2 - b * G3;
                const float* cr = g_ctx + b * D;
                const float4* wr = reinterpret_cast<const float4*>(W_ih + (size_t)k * (2 * D) + D);
                float acc = b_ih[k];
#pragma unroll 8
                for (int q = 0; q < D / 4; ++q) {
                    float4 wv = wr[q];
                    acc += __ldcg(&cr[q * 4 + 0]) * wv.x + __ldcg(&cr[q * 4 + 1]) * wv.y +
                           __ldcg(&cr[q * 4 + 2]) * wv.z + __ldcg(&cr[q * 4 + 3]) * wv.w;
                }
                g_gic[o2] = acc;
            }
        }
    }
    gbar(epoch);

    // ---- main loop ----
    if (light) main_loop<2>(sm, tid, cta, jbase, b_hh, W_out, b_out, out, epoch);
    else       main_loop<4>(sm, tid, cta, jbase, b_hh, W_out, b_out, out, epoch);
}

extern "C" void kernel_launch(void* const* d_in, const int* in_sizes, int n_in,
                              void* d_out, int out_size) {
    const float* enc    = (const float*)d_in[0];
    const float* emb    = (const float*)d_in[1];
    const float* W_attn = (const float*)d_in[2];
    const float* b_attn = (const float*)d_in[3];
    const float* W_ih   = (const float*)d_in[4];
    const float* W_hh   = (const float*)d_in[5];
    const float* b_ih   = (const float*)d_in[6];
    const float* b_hh   = (const float*)d_in[7];
    const float* W_out  = (const float*)d_in[8];
    const float* b_out  = (const float*)d_in[9];
    float* out = (float*)d_out;

    cudaFuncSetAttribute(decoder_kernel, cudaFuncAttributeMaxDynamicSharedMemorySize, SMEM_BYTES);
    reset_kernel<<<1, 1>>>();
    decoder_kernel<<<NC, NT, SMEM_BYTES>>>(enc, emb, W_attn, b_attn, W_ih, W_hh,
                                           b_ih, b_hh, W_out, b_out, out);
}